// round 14
// baseline (speedup 1.0000x reference)
#include <cuda_runtime.h>
#include <cstdint>

// DenseRoutingMaskLayer: per-row argmax over 8 routing logits selects a
// contiguous 512-float chunk of the 4096-wide input row.
//   inputs:          [B=16384, D=4096] f32   (d_in[0])
//   routing_inputs:  [B=16384, R=8]    f32   (d_in[1])
//   out:             [B=16384, W=512]  f32
//
// Round 14: R8 form with ONE change: __stwt (write-through) stores instead
// of __stcs. Write-through skips L2 line allocation for the 32MB output
// stream entirely, freeing L2 capacity/bandwidth for the read stream.
// All measured variants (R1/R7/R8/R10/R11/R13) are within run-to-run noise
// (+-0.5us) at the ~6.2 TB/s traffic roofline; this is the last untested
// mechanism that changes L2-side traffic rather than scheduling.
//  - 1 row per warp, 8 warps/CTA, grid 2048; regs ~24, occ ~70%.
//  - argmax via two uniform float4 broadcast loads + branchless depth-3
//    comparison tree; strict '>' keeps the lower index == jnp.argmax
//    first-occurrence tie-break.
//  - 4x __ldcg reads batched before 4x __stwt writes.

struct VI { float v; int i; };

__device__ __forceinline__ VI vmax(VI a, VI b) {
    // b has the higher index; keep a on ties -> first occurrence wins
    VI r;
    r.v = (b.v > a.v) ? b.v : a.v;
    r.i = (b.v > a.v) ? b.i : a.i;
    return r;
}

__global__ __launch_bounds__(256, 8)
void dense_routing_mask_kernel(const float* __restrict__ inputs,
                               const float* __restrict__ routing,
                               float* __restrict__ out) {
    const int warp = threadIdx.x >> 5;
    const int lane = threadIdx.x & 31;
    const int row  = blockIdx.x * 8 + warp;

    // ---- argmax: all lanes load the same 8 logits (broadcast) ----
    const float4* r4 = reinterpret_cast<const float4*>(routing) + row * 2;
    const float4 a = __ldg(r4);
    const float4 b = __ldg(r4 + 1);

    VI m01 = vmax(VI{a.x, 0}, VI{a.y, 1});
    VI m23 = vmax(VI{a.z, 2}, VI{a.w, 3});
    VI m45 = vmax(VI{b.x, 4}, VI{b.y, 5});
    VI m67 = vmax(VI{b.z, 6}, VI{b.w, 7});
    VI m03 = vmax(m01, m23);
    VI m47 = vmax(m45, m67);
    const int idx = vmax(m03, m47).i;

    // ---- copy the selected 512-float chunk: 128 float4, 4 per lane ----
    const float4* __restrict__ src = reinterpret_cast<const float4*>(inputs)
        + row * 1024 + idx * 128;
    float4* __restrict__ dst = reinterpret_cast<float4*>(out) + row * 128;

    float4 t0 = __ldcg(src + lane);
    float4 t1 = __ldcg(src + lane + 32);
    float4 t2 = __ldcg(src + lane + 64);
    float4 t3 = __ldcg(src + lane + 96);

    __stwt(dst + lane,      t0);
    __stwt(dst + lane + 32, t1);
    __stwt(dst + lane + 64, t2);
    __stwt(dst + lane + 96, t3);
}

extern "C" void kernel_launch(void* const* d_in, const int* in_sizes, int n_in,
                              void* d_out, int out_size) {
    const float* inputs  = (const float*)d_in[0];
    const float* routing = (const float*)d_in[1];
    float* out = (float*)d_out;

    const int B = in_sizes[1] / 8;   // 16384
    const int blocks = B / 8;        // 2048 (8 warps per CTA, 1 row per warp)

    dense_routing_mask_kernel<<<blocks, 256>>>(inputs, routing, out);
}

// round 15
// speedup vs baseline: 1.0552x; 1.0552x over previous
#include <cuda_runtime.h>
#include <cstdint>

// DenseRoutingMaskLayer: per-row argmax over 8 routing logits selects a
// contiguous 512-float chunk of the 4096-wide input row.
//   inputs:          [B=16384, D=4096] f32   (d_in[0])
//   routing_inputs:  [B=16384, R=8]    f32   (d_in[1])
//   out:             [B=16384, W=512]  f32
//
// FINAL (R8 form; best measured 10.40us, replicates 10.66-10.91us).
// The kernel sits at the memory service-rate roofline: 64.5MB mandatory
// traffic (0.5MB routing + 32MB gathered reads + 32MB writes) at
// ~6.2 TB/s combined. 14 rounds of single-variable experiments confirmed
// no remaining lever moves it beyond run-to-run noise:
//   - higher occupancy / half-row warps (R5):      +1.6us
//   - register-buffered multi-row MLP (R2/R4):     +0.4..0.8us
//   - cp.async.bulk TMA copy engine (R3):          +1.9us
//   - prologue elimination (R7):                   neutral
//   - 256-bit LDG/STG (R11):                       neutral/slightly worse
//   - evict-last reads (R10), write-through (R14): neutral
//   - single-wave grid, sequential rows (R12):     +0.6us
//
// Structure:
//  - 1 row per warp, 8 warps/CTA, grid 2048; regs 24, occ ~70%.
//  - argmax via two uniform float4 broadcast loads (all lanes read the
//    same 32B -> 1 sector, L1-broadcast) + branchless depth-3 comparison
//    tree; strict '>' keeps the lower index, matching jnp.argmax
//    first-occurrence tie-break.
//  - chunk copy: 4x __ldcg (L2-cached, L1-bypass reads) batched before
//    4x __stcs (evict-first writes) -> 4 independent 128B lines in flight
//    per lane-group with minimal register pressure.

struct VI { float v; int i; };

__device__ __forceinline__ VI vmax(VI a, VI b) {
    // b has the higher index; keep a on ties -> first occurrence wins
    VI r;
    r.v = (b.v > a.v) ? b.v : a.v;
    r.i = (b.v > a.v) ? b.i : a.i;
    return r;
}

__global__ __launch_bounds__(256, 8)
void dense_routing_mask_kernel(const float* __restrict__ inputs,
                               const float* __restrict__ routing,
                               float* __restrict__ out) {
    const int warp = threadIdx.x >> 5;
    const int lane = threadIdx.x & 31;
    const int row  = blockIdx.x * 8 + warp;

    // ---- argmax: all lanes load the same 8 logits (broadcast) ----
    const float4* r4 = reinterpret_cast<const float4*>(routing) + row * 2;
    const float4 a = __ldg(r4);
    const float4 b = __ldg(r4 + 1);

    VI m01 = vmax(VI{a.x, 0}, VI{a.y, 1});
    VI m23 = vmax(VI{a.z, 2}, VI{a.w, 3});
    VI m45 = vmax(VI{b.x, 4}, VI{b.y, 5});
    VI m67 = vmax(VI{b.z, 6}, VI{b.w, 7});
    VI m03 = vmax(m01, m23);
    VI m47 = vmax(m45, m67);
    const int idx = vmax(m03, m47).i;

    // ---- copy the selected 512-float chunk: 128 float4, 4 per lane ----
    const float4* __restrict__ src = reinterpret_cast<const float4*>(inputs)
        + row * 1024 + idx * 128;
    float4* __restrict__ dst = reinterpret_cast<float4*>(out) + row * 128;

    float4 t0 = __ldcg(src + lane);
    float4 t1 = __ldcg(src + lane + 32);
    float4 t2 = __ldcg(src + lane + 64);
    float4 t3 = __ldcg(src + lane + 96);

    __stcs(dst + lane,      t0);
    __stcs(dst + lane + 32, t1);
    __stcs(dst + lane + 64, t2);
    __stcs(dst + lane + 96, t3);
}

extern "C" void kernel_launch(void* const* d_in, const int* in_sizes, int n_in,
                              void* d_out, int out_size) {
    const float* inputs  = (const float*)d_in[0];
    const float* routing = (const float*)d_in[1];
    float* out = (float*)d_out;

    const int B = in_sizes[1] / 8;   // 16384
    const int blocks = B / 8;        // 2048 (8 warps per CTA, 1 row per warp)

    dense_routing_mask_kernel<<<blocks, 256>>>(inputs, routing, out);
}